// round 9
// baseline (speedup 1.0000x reference)
#include <cuda_runtime.h>
#include <cstdint>

// VectorQuantizer: input (16, 64, 8192) fp32, codebook (1024, 64) fp32
// score(n,k) = 0.5*||e_k||^2 - x_n . e_k   (argmin-equivalent to ||x - e||^2)
//
// R9: register-tiled fp32x2 GEMM, thread tile = 4 tokens x 8 codes, TPB=256
// -> 16 warps/SM (2 CTAs), ~115 regs (no spill). Float-compare epilogue with
// explicit index tie-break (matches jnp.argmin first-occurrence).

#define Dd 64
#define Kk 1024
#define Bb 16
#define Tt 8192
#define Nn (Bb * Tt)             // 131072 tokens
#define TPB 256
#define TOK_PER_CTA 128
#define CK 64                    // codes per chunk
#define NCHUNK (Kk / CK)         // 16

// E image: 8-entry code groups, 32 dpairs * 64B + 16B pad (stride == 16 mod 128)
#define EGSTRIDE 2064
#define CHUNK_BYTES (8 * EGSTRIDE)       // 16512
// X image: 4-token groups, 32 dpairs * 32B + 16B pad
#define XGSTRIDE 1040
#define XBYTES (32 * XGSTRIDE)           // 33280
#define XOFF 0
#define EOFF0 XBYTES
#define EOFF1 (EOFF0 + CHUNK_BYTES)
#define HOFF  (EOFF1 + CHUNK_BYTES)      // 66304
#define IOFF  (HOFF + 4096)              // 70400
#define SMEM_BYTES (IOFF + 512)          // 70912

__device__ float g_half[Kk];
__device__ __align__(16) unsigned char g_cbT[NCHUNK * CHUNK_BYTES];

typedef unsigned long long u64;

// ---- packed f32x2 helpers ----
__device__ __forceinline__ u64 pk2(float a, float b) {
    u64 r; asm("mov.b64 %0, {%1, %2};" : "=l"(r) : "f"(a), "f"(b)); return r;
}
__device__ __forceinline__ void fma2(u64& acc, u64 a, u64 b) {
    asm("fma.rn.f32x2 %0, %1, %2, %0;" : "+l"(acc) : "l"(a), "l"(b));
}
__device__ __forceinline__ float hsum2(u64 v) {
    float lo, hi; asm("mov.b64 {%0, %1}, %2;" : "=f"(lo), "=f"(hi) : "l"(v));
    return lo + hi;
}

// ---- cp.async helpers ----
__device__ __forceinline__ void cp16(uint32_t dst, const void* src) {
    uint64_t g = __cvta_generic_to_global(src);
    asm volatile("cp.async.cg.shared.global [%0], [%1], 16;" :: "r"(dst), "l"(g) : "memory");
}
__device__ __forceinline__ void cp_commit() { asm volatile("cp.async.commit_group;" ::: "memory"); }
template <int N>
__device__ __forceinline__ void cp_wait() { asm volatile("cp.async.wait_group %0;" :: "n"(N) : "memory"); }

__device__ __forceinline__ uint32_t s2u(const void* p) {
    uint32_t a;
    asm("{ .reg .u64 t; cvta.to.shared.u64 t, %1; cvt.u32.u64 %0, t; }" : "=r"(a) : "l"(p));
    return a;
}

// ---- prologue: 0.5||e||^2 + padded transposed codebook image ----
__global__ void vq_pre(const float* __restrict__ cb) {
    int k = blockIdx.x * blockDim.x + threadIdx.x;
    if (k >= Kk) return;
    const float* row = cb + k * Dd;
    float s = 0.f;
    unsigned char* dst = g_cbT + (k >> 6) * CHUNK_BYTES + ((k >> 3) & 7) * EGSTRIDE + (k & 7) * 8;
#pragma unroll
    for (int i = 0; i < 32; i++) {
        float a = row[2 * i], b = row[2 * i + 1];
        s += a * a + b * b;
        *(u64*)(dst + i * 64) = pk2(a, b);
    }
    g_half[k] = 0.5f * s;
}

__global__ __launch_bounds__(TPB, 2)
void vq_main(const float* __restrict__ input, const float* __restrict__ cb,
             float* __restrict__ out, float* __restrict__ out_idx) {
    extern __shared__ __align__(16) unsigned char smem[];
    const uint32_t sb = s2u(smem);

    const int tid = threadIdx.x;
    const int kl  = tid & 7;        // code lane: 8 codes
    const int ml  = tid >> 3;       // token group: 4 tokens (0..31)
    const int tile = blockIdx.x;    // 0..1023
    const int b    = tile >> 6;
    const int tb   = (tile & 63) * TOK_PER_CTA;

    // prefetch codebook chunk 0
#pragma unroll
    for (int s = 0; s < 5; s++) {
        int idx = tid + s * TPB;
        if (idx < CHUNK_BYTES / 16)
            cp16(sb + EOFF0 + idx * 16, g_cbT + idx * 16);
    }
    cp_commit();

    // stage X tile: 2 threads per token (half = 16 dpairs each)
    {
        const int tok = tid >> 1, hf = tid & 1;
        const float* inb = input + (size_t)b * Dd * Tt + tb + tok;
        unsigned char* xdst = smem + XOFF + (tok >> 2) * XGSTRIDE + (tok & 3) * 8;
#pragma unroll 8
        for (int i = hf * 16; i < hf * 16 + 16; i++) {
            float a = inb[(size_t)(2 * i) * Tt];
            float c = inb[(size_t)(2 * i + 1) * Tt];
            *(u64*)(xdst + i * 32) = pk2(a, c);
        }
    }
    {
        float* sH = (float*)(smem + HOFF);
#pragma unroll
        for (int i = tid; i < Kk; i += TPB) sH[i] = g_half[i];
    }

    float bs[4];
    int   bi[4];
#pragma unroll
    for (int m = 0; m < 4; m++) { bs[m] = 3.4e38f; bi[m] = 0; }

    const unsigned char* Xb = smem + XOFF + ml * XGSTRIDE;
    const float* sH = (const float*)(smem + HOFF);

    for (int c = 0; c < NCHUNK; c++) {
        const int st = c & 1;
        if (c + 1 < NCHUNK) {
            const uint32_t nxt = sb + (st ? EOFF0 : EOFF1);
            const unsigned char* src = g_cbT + (size_t)(c + 1) * CHUNK_BYTES;
#pragma unroll
            for (int s = 0; s < 5; s++) {
                int idx = tid + s * TPB;
                if (idx < CHUNK_BYTES / 16)
                    cp16(nxt + idx * 16, src + idx * 16);
            }
            cp_commit();
            cp_wait<1>();
        } else {
            cp_wait<0>();
        }
        __syncthreads();

        const unsigned char* Eb = smem + (st ? EOFF1 : EOFF0) + kl * EGSTRIDE;

        u64 acc[4][8];
#pragma unroll
        for (int m = 0; m < 4; m++)
#pragma unroll
            for (int k = 0; k < 8; k++) acc[m][k] = 0;

#pragma unroll 4
        for (int i = 0; i < 32; i++) {
            ulonglong2 xa = *(const ulonglong2*)(Xb + i * 32);
            ulonglong2 xb = *(const ulonglong2*)(Xb + i * 32 + 16);
            ulonglong2 e0 = *(const ulonglong2*)(Eb + i * 64);
            ulonglong2 e1 = *(const ulonglong2*)(Eb + i * 64 + 16);
            ulonglong2 e2 = *(const ulonglong2*)(Eb + i * 64 + 32);
            ulonglong2 e3 = *(const ulonglong2*)(Eb + i * 64 + 48);
            u64 xv[4] = {xa.x, xa.y, xb.x, xb.y};
            u64 ev[8] = {e0.x, e0.y, e1.x, e1.y, e2.x, e2.y, e3.x, e3.y};
#pragma unroll
            for (int m = 0; m < 4; m++)
#pragma unroll
                for (int k = 0; k < 8; k++)
                    fma2(acc[m][k], xv[m], ev[k]);
        }

        // fold into per-token best (within thread: ascending code index,
        // strict < keeps first occurrence)
        const int cbase = c * CK + kl * 8;
        float hs[8];
#pragma unroll
        for (int k = 0; k < 8; k++) hs[k] = sH[cbase + k];
#pragma unroll
        for (int m = 0; m < 4; m++) {
#pragma unroll
            for (int k = 0; k < 8; k++) {
                float s = hs[k] - hsum2(acc[m][k]);
                if (s < bs[m]) { bs[m] = s; bi[m] = cbase + k; }
            }
        }
        __syncthreads();   // protect E buffer before next prefetch lands
    }

    // reduce across the 8 code-lanes; exact-score ties -> smaller index
#pragma unroll
    for (int off = 1; off < 8; off <<= 1) {
#pragma unroll
        for (int m = 0; m < 4; m++) {
            float os = __shfl_xor_sync(0xffffffffu, bs[m], off);
            int   oi = __shfl_xor_sync(0xffffffffu, bi[m], off);
            if (os < bs[m] || (os == bs[m] && oi < bi[m])) { bs[m] = os; bi[m] = oi; }
        }
    }
    int* sIdx = (int*)(smem + IOFF);
    if (kl == 0) {
#pragma unroll
        for (int m = 0; m < 4; m++) sIdx[ml * 4 + m] = bi[m];
    }
    __syncthreads();

    // scatter: 2 threads per token, 32 dims each
    {
        const int tok = tid >> 1, hf = tid & 1;
        const int bidx = sIdx[tok];
        float* ob = out + (size_t)b * Dd * Tt + (size_t)(hf * 32) * Tt + tb + tok;
        const float4* cv = (const float4*)(cb + (size_t)bidx * Dd + hf * 32);
#pragma unroll
        for (int i = 0; i < 8; i++) {
            float4 v = cv[i];
            ob[(size_t)(4 * i + 0) * Tt] = v.x;
            ob[(size_t)(4 * i + 1) * Tt] = v.y;
            ob[(size_t)(4 * i + 2) * Tt] = v.z;
            ob[(size_t)(4 * i + 3) * Tt] = v.w;
        }
        if (out_idx != nullptr && hf == 0)
            out_idx[(size_t)b * Tt + tb + tok] = (float)bidx;
    }
}

extern "C" void kernel_launch(void* const* d_in, const int* in_sizes, int n_in,
                              void* d_out, int out_size) {
    const float* input = (const float*)d_in[0];   // (16, 64, 8192) fp32
    const float* cb    = (const float*)d_in[1];   // (1024, 64) fp32
    float* out = (float*)d_out;

    float* out_idx = nullptr;
    if (out_size >= (int)((long)Nn * Dd + Nn)) out_idx = out + (long)Nn * Dd;

    cudaFuncSetAttribute(vq_main, cudaFuncAttributeMaxDynamicSharedMemorySize, SMEM_BYTES);

    vq_pre<<<(Kk + 127) / 128, 128>>>(cb);
    vq_main<<<Nn / TOK_PER_CTA, TPB, SMEM_BYTES>>>(input, cb, out, out_idx);
}

// round 10
// speedup vs baseline: 1.0993x; 1.0993x over previous
#include <cuda_runtime.h>
#include <cstdint>

// VectorQuantizer: input (16, 64, 8192) fp32, codebook (1024, 64) fp32
// score(n,k) = 0.5*||e_k||^2 - x_n . e_k   (argmin-equivalent to ||x - e||^2)
//
// R10 = R8's 8x8 register-tiled fp32x2 GEMM core (214 regs, 8:1 FFMA2:LDS),
// repackaged: TPB=64, 64 tokens/CTA, grid=2048, launch_bounds(64,4)
// -> 16 warps/SM with NO register cap. Float-compare epilogue w/ index
// tie-break (R9-verified) replaces u64 key packing.

#define Dd 64
#define Kk 1024
#define Bb 16
#define Tt 8192
#define Nn (Bb * Tt)             // 131072 tokens
#define TPB 64
#define TOK_PER_CTA 64
#define CK 64                    // codes per chunk
#define NCHUNK (Kk / CK)         // 16

#define GSTRIDE 2064             // 8-entry group: 32 dpairs*64B + 16B pad (== 16 mod 128)
#define CHUNK_BYTES (8 * GSTRIDE)        // 16512
#define XOFF 0                   // X image: 8 groups
#define XBYTES (8 * GSTRIDE)             // 16512
#define EOFF0 XBYTES
#define EOFF1 (EOFF0 + CHUNK_BYTES)      // 33024
#define HOFF  (EOFF1 + CHUNK_BYTES)      // 49536
#define IOFF  (HOFF + 4096)              // 53632
#define SMEM_BYTES (IOFF + 512)          // 54144

__device__ float g_half[Kk];
__device__ __align__(16) unsigned char g_cbT[NCHUNK * CHUNK_BYTES];

typedef unsigned long long u64;

// ---- packed f32x2 helpers ----
__device__ __forceinline__ u64 pk2(float a, float b) {
    u64 r; asm("mov.b64 %0, {%1, %2};" : "=l"(r) : "f"(a), "f"(b)); return r;
}
__device__ __forceinline__ void fma2(u64& acc, u64 a, u64 b) {
    asm("fma.rn.f32x2 %0, %1, %2, %0;" : "+l"(acc) : "l"(a), "l"(b));
}
__device__ __forceinline__ float hsum2(u64 v) {
    float lo, hi; asm("mov.b64 {%0, %1}, %2;" : "=f"(lo), "=f"(hi) : "l"(v));
    return lo + hi;
}

// ---- cp.async helpers ----
__device__ __forceinline__ void cp16(uint32_t dst, const void* src) {
    uint64_t g = __cvta_generic_to_global(src);
    asm volatile("cp.async.cg.shared.global [%0], [%1], 16;" :: "r"(dst), "l"(g) : "memory");
}
__device__ __forceinline__ void cp_commit() { asm volatile("cp.async.commit_group;" ::: "memory"); }
template <int N>
__device__ __forceinline__ void cp_wait() { asm volatile("cp.async.wait_group %0;" :: "n"(N) : "memory"); }

__device__ __forceinline__ uint32_t s2u(const void* p) {
    uint32_t a;
    asm("{ .reg .u64 t; cvta.to.shared.u64 t, %1; cvt.u32.u64 %0, t; }" : "=r"(a) : "l"(p));
    return a;
}

// ---- prologue: 0.5||e||^2 + padded transposed codebook image ----
__global__ void vq_pre(const float* __restrict__ cb) {
    int k = blockIdx.x * blockDim.x + threadIdx.x;
    if (k >= Kk) return;
    const float* row = cb + k * Dd;
    float s = 0.f;
    unsigned char* dst = g_cbT + (k >> 6) * CHUNK_BYTES + ((k >> 3) & 7) * GSTRIDE + (k & 7) * 8;
#pragma unroll
    for (int i = 0; i < 32; i++) {
        float a = row[2 * i], b = row[2 * i + 1];
        s += a * a + b * b;
        *(u64*)(dst + i * 64) = pk2(a, b);
    }
    g_half[k] = 0.5f * s;
}

__global__ __launch_bounds__(TPB, 4)
void vq_main(const float* __restrict__ input, const float* __restrict__ cb,
             float* __restrict__ out, float* __restrict__ out_idx) {
    extern __shared__ __align__(16) unsigned char smem[];
    const uint32_t sb = s2u(smem);

    const int tid = threadIdx.x;
    const int kl  = tid & 7;        // code lane (8 codes)
    const int ml  = tid >> 3;       // token group (8 tokens)
    const int tile = blockIdx.x;    // 0..2047
    const int b    = tile >> 7;     // 128 tiles per batch
    const int tb   = (tile & 127) * TOK_PER_CTA;

    // prefetch codebook chunk 0
#pragma unroll
    for (int s = 0; s < 17; s++) {
        int idx = tid + s * TPB;
        if (idx < CHUNK_BYTES / 16)
            cp16(sb + EOFF0 + idx * 16, g_cbT + idx * 16);
    }
    cp_commit();

    // stage X tile: thread tid stages token tb + tid
    {
        const float* inb = input + (size_t)b * Dd * Tt + tb + tid;
        unsigned char* xdst = smem + XOFF + (tid >> 3) * GSTRIDE + (tid & 7) * 8;
#pragma unroll 8
        for (int i = 0; i < 32; i++) {
            float a = inb[(size_t)(2 * i) * Tt];
            float c = inb[(size_t)(2 * i + 1) * Tt];
            *(u64*)(xdst + i * 64) = pk2(a, c);
        }
    }
    {
        float* sH = (float*)(smem + HOFF);
#pragma unroll
        for (int i = tid; i < Kk; i += TPB) sH[i] = g_half[i];
    }

    float bs[8];
    int   bi[8];
#pragma unroll
    for (int m = 0; m < 8; m++) { bs[m] = 3.4e38f; bi[m] = 0; }

    const unsigned char* Xb = smem + XOFF + ml * GSTRIDE;
    const float* sH = (const float*)(smem + HOFF);

    for (int c = 0; c < NCHUNK; c++) {
        const int st = c & 1;
        if (c + 1 < NCHUNK) {
            const uint32_t nxt = sb + (st ? EOFF0 : EOFF1);
            const unsigned char* src = g_cbT + (size_t)(c + 1) * CHUNK_BYTES;
#pragma unroll
            for (int s = 0; s < 17; s++) {
                int idx = tid + s * TPB;
                if (idx < CHUNK_BYTES / 16)
                    cp16(nxt + idx * 16, src + idx * 16);
            }
            cp_commit();
            cp_wait<1>();
        } else {
            cp_wait<0>();
        }
        __syncthreads();

        const unsigned char* Eb = smem + (st ? EOFF1 : EOFF0) + kl * GSTRIDE;

        u64 acc[8][8];
#pragma unroll
        for (int m = 0; m < 8; m++)
#pragma unroll
            for (int k = 0; k < 8; k++) acc[m][k] = 0;

#pragma unroll 4
        for (int i = 0; i < 32; i++) {
            ulonglong2 x0 = *(const ulonglong2*)(Xb + i * 64);
            ulonglong2 x1 = *(const ulonglong2*)(Xb + i * 64 + 16);
            ulonglong2 x2 = *(const ulonglong2*)(Xb + i * 64 + 32);
            ulonglong2 x3 = *(const ulonglong2*)(Xb + i * 64 + 48);
            ulonglong2 e0 = *(const ulonglong2*)(Eb + i * 64);
            ulonglong2 e1 = *(const ulonglong2*)(Eb + i * 64 + 16);
            ulonglong2 e2 = *(const ulonglong2*)(Eb + i * 64 + 32);
            ulonglong2 e3 = *(const ulonglong2*)(Eb + i * 64 + 48);
            u64 xv[8] = {x0.x, x0.y, x1.x, x1.y, x2.x, x2.y, x3.x, x3.y};
            u64 ev[8] = {e0.x, e0.y, e1.x, e1.y, e2.x, e2.y, e3.x, e3.y};
#pragma unroll
            for (int m = 0; m < 8; m++)
#pragma unroll
                for (int k = 0; k < 8; k++)
                    fma2(acc[m][k], xv[m], ev[k]);
        }

        // fold: within thread codes ascend, strict < keeps first occurrence
        const int cbase = c * CK + kl * 8;
        float hs[8];
#pragma unroll
        for (int k = 0; k < 8; k++) hs[k] = sH[cbase + k];
#pragma unroll
        for (int m = 0; m < 8; m++) {
#pragma unroll
            for (int k = 0; k < 8; k++) {
                float s = hs[k] - hsum2(acc[m][k]);
                if (s < bs[m]) { bs[m] = s; bi[m] = cbase + k; }
            }
        }
        __syncthreads();   // protect E buffer before next prefetch lands
    }

    // reduce across the 8 code-lanes; exact-score ties -> smaller index
#pragma unroll
    for (int off = 1; off < 8; off <<= 1) {
#pragma unroll
        for (int m = 0; m < 8; m++) {
            float os = __shfl_xor_sync(0xffffffffu, bs[m], off);
            int   oi = __shfl_xor_sync(0xffffffffu, bi[m], off);
            if (os < bs[m] || (os == bs[m] && oi < bi[m])) { bs[m] = os; bi[m] = oi; }
        }
    }
    int* sIdx = (int*)(smem + IOFF);
    if (kl == 0) {
#pragma unroll
        for (int m = 0; m < 8; m++) sIdx[ml * 8 + m] = bi[m];
    }
    __syncthreads();

    // scatter: thread tid owns token tb + tid
    {
        const int bidx = sIdx[tid];
        const int t = tb + tid;
        float* ob = out + (size_t)b * Dd * Tt + t;
        const float4* cv = (const float4*)(cb + (size_t)bidx * Dd);
#pragma unroll
        for (int i = 0; i < Dd / 4; i++) {
            float4 v = cv[i];
            ob[(size_t)(4 * i + 0) * Tt] = v.x;
            ob[(size_t)(4 * i + 1) * Tt] = v.y;
            ob[(size_t)(4 * i + 2) * Tt] = v.z;
            ob[(size_t)(4 * i + 3) * Tt] = v.w;
        }
        if (out_idx != nullptr) out_idx[(size_t)b * Tt + t] = (float)bidx;
    }
}

extern "C" void kernel_launch(void* const* d_in, const int* in_sizes, int n_in,
                              void* d_out, int out_size) {
    const float* input = (const float*)d_in[0];   // (16, 64, 8192) fp32
    const float* cb    = (const float*)d_in[1];   // (1024, 64) fp32
    float* out = (float*)d_out;

    float* out_idx = nullptr;
    if (out_size >= (int)((long)Nn * Dd + Nn)) out_idx = out + (long)Nn * Dd;

    cudaFuncSetAttribute(vq_main, cudaFuncAttributeMaxDynamicSharedMemorySize, SMEM_BYTES);

    vq_pre<<<(Kk + 127) / 128, 128>>>(cb);
    vq_main<<<Nn / TOK_PER_CTA, TPB, SMEM_BYTES>>>(input, cb, out, out_idx);
}

// round 11
// speedup vs baseline: 1.1006x; 1.0012x over previous
#include <cuda_runtime.h>
#include <cstdint>

// VectorQuantizer: input (16, 64, 8192) fp32, codebook (1024, 64) fp32
// score(n,k) = 0.5*||e_k||^2 - x_n . e_k   (argmin-equivalent to ||x - e||^2)
//
// R11: 4 tokens x 8 codes register tile (~150 regs natural), TPB=128,
// launch_bounds(128,3) -> 170-reg cap (no spill) and 12 warps/SM =
// 3 warps/SMSP, vs the 8x8 tile's regfile-capped 8 warps. 5.3:1 FFMA2:LDS.

#define Dd 64
#define Kk 1024
#define Bb 16
#define Tt 8192
#define Nn (Bb * Tt)             // 131072 tokens
#define TPB 128
#define TOK_PER_CTA 64
#define CK 64                    // codes per chunk
#define NCHUNK (Kk / CK)         // 16

// E image: 8-entry code groups, 32 dpairs * 64B + 16B pad (stride == 16 mod 128)
#define EGSTRIDE 2064
#define CHUNK_BYTES (8 * EGSTRIDE)       // 16512
// X image: 4-token groups, 32 dpairs * 32B + 16B pad
#define XGSTRIDE 1040
#define XBYTES (16 * XGSTRIDE)           // 16640
#define XOFF 0
#define EOFF0 XBYTES
#define EOFF1 (EOFF0 + CHUNK_BYTES)      // 33152
#define HOFF  (EOFF1 + CHUNK_BYTES)      // 49664
#define IOFF  (HOFF + 4096)              // 53760
#define SMEM_BYTES (IOFF + 512)          // 54272

__device__ float g_half[Kk];
__device__ __align__(16) unsigned char g_cbT[NCHUNK * CHUNK_BYTES];

typedef unsigned long long u64;

// ---- packed f32x2 helpers ----
__device__ __forceinline__ u64 pk2(float a, float b) {
    u64 r; asm("mov.b64 %0, {%1, %2};" : "=l"(r) : "f"(a), "f"(b)); return r;
}
__device__ __forceinline__ void fma2(u64& acc, u64 a, u64 b) {
    asm("fma.rn.f32x2 %0, %1, %2, %0;" : "+l"(acc) : "l"(a), "l"(b));
}
__device__ __forceinline__ float hsum2(u64 v) {
    float lo, hi; asm("mov.b64 {%0, %1}, %2;" : "=f"(lo), "=f"(hi) : "l"(v));
    return lo + hi;
}

// ---- cp.async helpers ----
__device__ __forceinline__ void cp16(uint32_t dst, const void* src) {
    uint64_t g = __cvta_generic_to_global(src);
    asm volatile("cp.async.cg.shared.global [%0], [%1], 16;" :: "r"(dst), "l"(g) : "memory");
}
__device__ __forceinline__ void cp_commit() { asm volatile("cp.async.commit_group;" ::: "memory"); }
template <int N>
__device__ __forceinline__ void cp_wait() { asm volatile("cp.async.wait_group %0;" :: "n"(N) : "memory"); }

__device__ __forceinline__ uint32_t s2u(const void* p) {
    uint32_t a;
    asm("{ .reg .u64 t; cvta.to.shared.u64 t, %1; cvt.u32.u64 %0, t; }" : "=r"(a) : "l"(p));
    return a;
}

// ---- prologue: 0.5||e||^2 + padded transposed codebook image ----
__global__ void vq_pre(const float* __restrict__ cb) {
    int k = blockIdx.x * blockDim.x + threadIdx.x;
    if (k >= Kk) return;
    const float* row = cb + k * Dd;
    float s = 0.f;
    unsigned char* dst = g_cbT + (k >> 6) * CHUNK_BYTES + ((k >> 3) & 7) * EGSTRIDE + (k & 7) * 8;
#pragma unroll
    for (int i = 0; i < 32; i++) {
        float a = row[2 * i], b = row[2 * i + 1];
        s += a * a + b * b;
        *(u64*)(dst + i * 64) = pk2(a, b);
    }
    g_half[k] = 0.5f * s;
}

__global__ __launch_bounds__(TPB, 3)
void vq_main(const float* __restrict__ input, const float* __restrict__ cb,
             float* __restrict__ out, float* __restrict__ out_idx) {
    extern __shared__ __align__(16) unsigned char smem[];
    const uint32_t sb = s2u(smem);

    const int tid = threadIdx.x;
    const int kl  = tid & 7;        // code lane: 8 codes
    const int ml  = tid >> 3;       // token group: 4 tokens (0..15)
    const int tile = blockIdx.x;    // 0..2047
    const int b    = tile >> 7;     // 128 tiles per batch
    const int tb   = (tile & 127) * TOK_PER_CTA;

    // prefetch codebook chunk 0
#pragma unroll
    for (int s = 0; s < 9; s++) {
        int idx = tid + s * TPB;
        if (idx < CHUNK_BYTES / 16)
            cp16(sb + EOFF0 + idx * 16, g_cbT + idx * 16);
    }
    cp_commit();

    // stage X tile: 2 threads per token (16 dpairs each)
    {
        const int tok = tid >> 1, hf = tid & 1;
        const float* inb = input + (size_t)b * Dd * Tt + tb + tok;
        unsigned char* xdst = smem + XOFF + (tok >> 2) * XGSTRIDE + (tok & 3) * 8;
#pragma unroll 8
        for (int i = hf * 16; i < hf * 16 + 16; i++) {
            float a = inb[(size_t)(2 * i) * Tt];
            float c = inb[(size_t)(2 * i + 1) * Tt];
            *(u64*)(xdst + i * 32) = pk2(a, c);
        }
    }
    {
        float* sH = (float*)(smem + HOFF);
#pragma unroll
        for (int i = tid; i < Kk; i += TPB) sH[i] = g_half[i];
    }

    float bs[4];
    int   bi[4];
#pragma unroll
    for (int m = 0; m < 4; m++) { bs[m] = 3.4e38f; bi[m] = 0; }

    const unsigned char* Xb = smem + XOFF + ml * XGSTRIDE;
    const float* sH = (const float*)(smem + HOFF);

    for (int c = 0; c < NCHUNK; c++) {
        const int st = c & 1;
        if (c + 1 < NCHUNK) {
            const uint32_t nxt = sb + (st ? EOFF0 : EOFF1);
            const unsigned char* src = g_cbT + (size_t)(c + 1) * CHUNK_BYTES;
#pragma unroll
            for (int s = 0; s < 9; s++) {
                int idx = tid + s * TPB;
                if (idx < CHUNK_BYTES / 16)
                    cp16(nxt + idx * 16, src + idx * 16);
            }
            cp_commit();
            cp_wait<1>();
        } else {
            cp_wait<0>();
        }
        __syncthreads();

        const unsigned char* Eb = smem + (st ? EOFF1 : EOFF0) + kl * EGSTRIDE;

        u64 acc[4][8];
#pragma unroll
        for (int m = 0; m < 4; m++)
#pragma unroll
            for (int k = 0; k < 8; k++) acc[m][k] = 0;

#pragma unroll 4
        for (int i = 0; i < 32; i++) {
            ulonglong2 xa = *(const ulonglong2*)(Xb + i * 32);
            ulonglong2 xb = *(const ulonglong2*)(Xb + i * 32 + 16);
            ulonglong2 e0 = *(const ulonglong2*)(Eb + i * 64);
            ulonglong2 e1 = *(const ulonglong2*)(Eb + i * 64 + 16);
            ulonglong2 e2 = *(const ulonglong2*)(Eb + i * 64 + 32);
            ulonglong2 e3 = *(const ulonglong2*)(Eb + i * 64 + 48);
            u64 xv[4] = {xa.x, xa.y, xb.x, xb.y};
            u64 ev[8] = {e0.x, e0.y, e1.x, e1.y, e2.x, e2.y, e3.x, e3.y};
#pragma unroll
            for (int m = 0; m < 4; m++)
#pragma unroll
                for (int k = 0; k < 8; k++)
                    fma2(acc[m][k], xv[m], ev[k]);
        }

        // fold: within thread codes ascend, strict < keeps first occurrence
        const int cbase = c * CK + kl * 8;
        float hs[8];
#pragma unroll
        for (int k = 0; k < 8; k++) hs[k] = sH[cbase + k];
#pragma unroll
        for (int m = 0; m < 4; m++) {
#pragma unroll
            for (int k = 0; k < 8; k++) {
                float s = hs[k] - hsum2(acc[m][k]);
                if (s < bs[m]) { bs[m] = s; bi[m] = cbase + k; }
            }
        }
        __syncthreads();   // protect E buffer before next prefetch lands
    }

    // reduce across the 8 code-lanes; exact-score ties -> smaller index
#pragma unroll
    for (int off = 1; off < 8; off <<= 1) {
#pragma unroll
        for (int m = 0; m < 4; m++) {
            float os = __shfl_xor_sync(0xffffffffu, bs[m], off);
            int   oi = __shfl_xor_sync(0xffffffffu, bi[m], off);
            if (os < bs[m] || (os == bs[m] && oi < bi[m])) { bs[m] = os; bi[m] = oi; }
        }
    }
    int* sIdx = (int*)(smem + IOFF);
    if (kl == 0) {
#pragma unroll
        for (int m = 0; m < 4; m++) sIdx[ml * 4 + m] = bi[m];
    }
    __syncthreads();

    // scatter: 2 threads per token, 32 dims each
    {
        const int tok = tid >> 1, hf = tid & 1;
        const int bidx = sIdx[tok];
        float* ob = out + (size_t)b * Dd * Tt + (size_t)(hf * 32) * Tt + tb + tok;
        const float4* cv = (const float4*)(cb + (size_t)bidx * Dd + hf * 32);
#pragma unroll
        for (int i = 0; i < 8; i++) {
            float4 v = cv[i];
            ob[(size_t)(4 * i + 0) * Tt] = v.x;
            ob[(size_t)(4 * i + 1) * Tt] = v.y;
            ob[(size_t)(4 * i + 2) * Tt] = v.z;
            ob[(size_t)(4 * i + 3) * Tt] = v.w;
        }
        if (out_idx != nullptr && hf == 0)
            out_idx[(size_t)b * Tt + tb + tok] = (float)bidx;
    }
}

extern "C" void kernel_launch(void* const* d_in, const int* in_sizes, int n_in,
                              void* d_out, int out_size) {
    const float* input = (const float*)d_in[0];   // (16, 64, 8192) fp32
    const float* cb    = (const float*)d_in[1];   // (1024, 64) fp32
    float* out = (float*)d_out;

    float* out_idx = nullptr;
    if (out_size >= (int)((long)Nn * Dd + Nn)) out_idx = out + (long)Nn * Dd;

    cudaFuncSetAttribute(vq_main, cudaFuncAttributeMaxDynamicSharedMemorySize, SMEM_BYTES);

    vq_pre<<<(Kk + 127) / 128, 128>>>(cb);
    vq_main<<<Nn / TOK_PER_CTA, TPB, SMEM_BYTES>>>(input, cb, out, out_idx);
}